// round 12
// baseline (speedup 1.0000x reference)
#include <cuda_runtime.h>
#include <cuda_bf16.h>
#include <cstdint>

#define Vn 55
#define Cn 64
#define Dn 64
#define Tn 128
#define Nn 64
#define VD 3520
#define TB 16                     // output t per block

#define RS 72                     // padded row stride in bf16 (36 words)

__device__ float2 d_mP[2048];             // mask pairs: [kp*64+u]
__device__ float2 d_AB1[4096];            // BN1 (scale, shift) packed, [d*64+u]
__device__ float2 d_AB2[Dn];              // BN2 (scale, shift) packed
__device__ __nv_bfloat16 d_WhB[64 * RS];  // W^T hi, [d*RS + c]
__device__ __nv_bfloat16 d_WlB[64 * RS];  // W^T lo residual

__device__ __forceinline__ void mma16(float* c, const unsigned* a, const unsigned* b) {
    asm volatile(
        "mma.sync.aligned.m16n8k16.row.col.f32.bf16.bf16.f32 "
        "{%0,%1,%2,%3}, {%4,%5,%6,%7}, {%8,%9}, {%0,%1,%2,%3};"
        : "+f"(c[0]), "+f"(c[1]), "+f"(c[2]), "+f"(c[3])
        : "r"(a[0]), "r"(a[1]), "r"(a[2]), "r"(a[3]), "r"(b[0]), "r"(b[1]));
}

// ---- prep: one-time tables -------------------------------------------------
__global__ __launch_bounds__(256) void prep_kernel(
    const float* __restrict__ W, const float* __restrict__ b,
    const float* __restrict__ fm,
    const float* __restrict__ g1, const float* __restrict__ be1,
    const float* __restrict__ m1, const float* __restrict__ v1,
    const float* __restrict__ g2, const float* __restrict__ be2,
    const float* __restrict__ m2, const float* __restrict__ v2)
{
    int i = blockIdx.x * 256 + threadIdx.x;   // 0..4095
    if (i < 2048) {
        int kp = i >> 6, u = i & 63;
        float m0 = 0.0f, m1v = 0.0f;
        if (u < Vn) {
            m0 = tanhf(fm[u * Cn + 2 * kp]) + 1.0f;
            m1v = tanhf(fm[u * Cn + 2 * kp + 1]) + 1.0f;
        }
        d_mP[i] = make_float2(m0, m1v);
    }
    if (i < 4096) {
        int c = i >> 6, d = i & 63;
        float w = W[i];
        __nv_bfloat16 h = __float2bfloat16(w);
        float lo = w - __bfloat162float(h);
        d_WhB[d * RS + c] = h;
        d_WlB[d * RS + c] = __float2bfloat16(lo);

        int u = i >> 6, dd = i & 63;
        float a = g1[i] * rsqrtf(v1[i] + 1e-5f);
        d_AB1[dd * 64 + u] = make_float2(a, be1[i] + a * (b[dd] - m1[i]));
    }
    if (i < Dn) {
        float a = g2[i] * rsqrtf(v2[i] + 1e-5f);
        d_AB2[i] = make_float2(a, be2[i] - a * m2[i]);
    }
}

// ---- fused, software-pipelined kernel --------------------------------------
// Block = (n, 16 t). Per iteration (single sync): build A(t+1) | GEMM+BN1(t)
// into 4-slot smem ring | emit out(t-2) from ring slots (t-3..t-1).
// Dyn smem: ring 4*3520*4 = 56320 | A bufs 2*(9216+9216) = 36864 | B 18432
#define SMEMF_BYTES (4 * VD * 4 + 4 * 9216 + 2 * 9216)   // 111616

__global__ __launch_bounds__(256) void fused_kernel(const float* __restrict__ x,
                                                    float* __restrict__ out)
{
    extern __shared__ __align__(16) char smraw[];
    float* ring = (float*)smraw;                               // 4 slabs
    char* Ab = smraw + 4 * VD * 4;                             // 2 x (AH,AL)
    __nv_bfloat16* BH = (__nv_bfloat16*)(Ab + 4 * 9216);       // [d*RS+k]
    __nv_bfloat16* BL = BH + 64 * RS;
    const unsigned* BHw = (const unsigned*)BH;
    const unsigned* BLw = (const unsigned*)BL;

    const int tid = threadIdx.x;
    const int n  = blockIdx.x >> 3;
    const int t0 = (blockIdx.x & 7) * TB;

    // Load W tiles once
    {
        float4* bh4 = (float4*)BH;
        float4* bl4 = (float4*)BL;
        const float4* gh4 = (const float4*)d_WhB;
        const float4* gl4 = (const float4*)d_WlB;
        for (int i = tid; i < 576; i += 256) { bh4[i] = gh4[i]; bl4[i] = gl4[i]; }
    }

    // Warp GEMM mapping (proven R9 layout + XOR swizzle)
    const int w = tid >> 5;
    const int lane = tid & 31;
    const int lr = lane >> 2;
    const int lc = lane & 3;
    const int ub = (w & 3) * 16;
    const int nb = (w >> 2) * 32;
    const int row0 = ub + lr;
    const int row1 = row0 + 8;
    const int lcs0 = lc ^ ((row0 >> 3) & 3);
    const int lcs1 = lc ^ ((row1 >> 3) & 3);

    const float* xn = x + (size_t)n * (Cn * Tn * Vn);
    float* outn = out + (size_t)n * (Cn * Tn * Vn);

    // Build A slab for time t into parity buffer (t&1)
    auto buildA = [&](int t) {
        unsigned* AHw = (unsigned*)(Ab + (t & 1) * 18432);
        unsigned* ALw = AHw + 2304;                 // +9216 bytes
        const float* xnt = xn + t * Vn;
#pragma unroll
        for (int r = 0; r < 8; r++) {
            int iw = tid + r * 256;
            int u  = (iw & 31) + ((iw >> 10) << 5);
            int kp = (iw >> 5) & 31;
            int k  = kp << 1;
            float v0 = 0.0f, v1 = 0.0f;
            if (u < Vn) {
                int s0 = u + k;
                if (s0 >= Vn) s0 -= Vn;
                if (s0 >= Vn) s0 -= Vn;
                int s1 = s0 + 1;
                if (s1 >= Vn) s1 -= Vn;
                float2 m2v = d_mP[kp * 64 + u];
                v0 = xnt[(size_t)k * (Tn * Vn) + s0] * m2v.x;
                v1 = xnt[(size_t)(k + 1) * (Tn * Vn) + s1] * m2v.y;
            }
            __nv_bfloat162 h2 = __float22bfloat162_rn(make_float2(v0, v1));
            float l0 = v0 - __bfloat162float(h2.x);
            float l1 = v1 - __bfloat162float(h2.y);
            __nv_bfloat162 l2 = __float22bfloat162_rn(make_float2(l0, l1));
            int kws = kp ^ ((u >> 3) & 3);
            AHw[u * 36 + kws] = *(unsigned*)&h2;
            ALw[u * 36 + kws] = *(unsigned*)&l2;
        }
    };

    // Prologue: build halo slab t0-1 (if it exists)
    if (t0 > 0) buildA(t0 - 1);
    __syncthreads();

#pragma unroll 1
    for (int it = 0; it < TB + 3; it++) {
        const int tg = t0 - 1 + it;          // slab being GEMM'd this iter

        // ---- stream 1: build A for next slab ----
        const int tn = tg + 1;
        if (tn <= t0 + TB && tn < Tn) buildA(tn);

        // ---- stream 2: GEMM(tg) + BN1 + inverse shift -> ring, or zero ----
        if (tg <= t0 + TB) {
            float* rs = ring + ((tg + 4) & 3) * VD;
            if ((unsigned)tg < (unsigned)Tn) {
                const unsigned* AHw = (const unsigned*)(Ab + (tg & 1) * 18432);
                const unsigned* ALw = AHw + 2304;

                float acc[4][4];
#pragma unroll
                for (int i = 0; i < 4; i++)
#pragma unroll
                    for (int j = 0; j < 4; j++) acc[i][j] = 0.0f;

#pragma unroll
                for (int s = 0; s < 4; s++) {
                    const int a0 = row0 * 36 + s * 8 + lcs0;
                    const int a1 = row1 * 36 + s * 8 + lcs1;
                    unsigned ah[4], al[4];
                    ah[0] = AHw[a0];
                    ah[1] = AHw[a1];
                    ah[2] = AHw[a0 + 4];
                    ah[3] = AHw[a1 + 4];
                    al[0] = ALw[a0];
                    al[1] = ALw[a1];
                    al[2] = ALw[a0 + 4];
                    al[3] = ALw[a1 + 4];
#pragma unroll
                    for (int ntile = 0; ntile < 4; ntile++) {
                        const int bbase = (nb + ntile * 8 + lr) * 36 + s * 8 + lc;
                        unsigned bh[2], bl[2];
                        bh[0] = BHw[bbase];
                        bh[1] = BHw[bbase + 4];
                        bl[0] = BLw[bbase];
                        bl[1] = BLw[bbase + 4];
                        mma16(acc[ntile], ah, bh);
                        mma16(acc[ntile], ah, bl);
                        mma16(acc[ntile], al, bh);
                    }
                }

#pragma unroll
                for (int i = 0; i < 4; i++) {
                    int u = ub + lr + ((i & 2) ? 8 : 0);
                    if (u < Vn) {
#pragma unroll
                        for (int ntile = 0; ntile < 4; ntile++) {
                            int d = nb + ntile * 8 + lc * 2 + (i & 1);
                            float2 ab = d_AB1[d * 64 + u];
                            float y = fmaxf(ab.x * acc[ntile][i] + ab.y, 0.0f);
                            int vv = u + d;
                            if (vv >= Vn) vv -= Vn;
                            if (vv >= Vn) vv -= Vn;
                            rs[d * Vn + vv] = y;
                        }
                    }
                }
            } else {
                for (int i = tid; i < VD; i += 256) rs[i] = 0.0f;
            }
        }

        // ---- stream 3: emit output for tm = tg-2 ----
        const int tm = tg - 2;
        if (tm >= t0) {
            for (int i = tid; i < VD; i += 256) {
                int c = i / 55;
                int v = i - c * 55;
                int off = (c % 3) - 1;
                int tt = tm + off;                       // in [t0-1, t0+TB]
                float gv = ring[((tt + 4) & 3) * VD + i];
                float2 ab = d_AB2[c];
                size_t a = (size_t)c * (Tn * Vn) + tm * Vn + v;
                outn[a] = fmaxf(ab.x * gv + ab.y + xn[a], 0.0f);
            }
        }
        __syncthreads();
    }
}

extern "C" void kernel_launch(void* const* d_in, const int* in_sizes, int n_in,
                              void* d_out, int out_size)
{
    const float* x   = (const float*)d_in[0];
    const float* W   = (const float*)d_in[1];
    const float* b   = (const float*)d_in[2];
    const float* fm  = (const float*)d_in[3];
    const float* g1  = (const float*)d_in[4];
    const float* be1 = (const float*)d_in[5];
    const float* m1  = (const float*)d_in[6];
    const float* v1  = (const float*)d_in[7];
    const float* g2  = (const float*)d_in[8];
    const float* be2 = (const float*)d_in[9];
    const float* m2  = (const float*)d_in[10];
    const float* v2  = (const float*)d_in[11];
    float* out = (float*)d_out;

    cudaFuncSetAttribute(fused_kernel, cudaFuncAttributeMaxDynamicSharedMemorySize,
                         SMEMF_BYTES);

    prep_kernel<<<16, 256>>>(W, b, fm, g1, be1, m1, v1, g2, be2, m2, v2);
    fused_kernel<<<Nn * (Tn / TB), 256, SMEMF_BYTES>>>(x, out);
}

// round 13
// speedup vs baseline: 1.4506x; 1.4506x over previous
#include <cuda_runtime.h>
#include <cuda_fp16.h>
#include <cstdint>

#define Vn 55
#define Cn 64
#define Dn 64
#define Tn 128
#define Nn 64
#define NTn 8192
#define VD 3520
#define TOTAL (NTn * VD)       // 28,835,840

#define RS 72                  // padded row stride in fp16 elements (36 words)

__device__ float g_buf[TOTAL];            // g in [n][d][t][v]  (same layout as x)
__device__ float2 d_mP[2048];             // mask pairs: [kp*64+u]
__device__ float2 d_AB1[4096];            // BN1 (scale, shift) packed, [d*64+u]
__device__ float d_A2[Dn];
__device__ float d_B2[Dn];
__device__ __half d_WhH[64 * RS];         // W^T fp16, [d*RS + c]

__device__ __forceinline__ void mma16(float* c, const unsigned* a, const unsigned* b) {
    asm volatile(
        "mma.sync.aligned.m16n8k16.row.col.f32.f16.f16.f32 "
        "{%0,%1,%2,%3}, {%4,%5,%6,%7}, {%8,%9}, {%0,%1,%2,%3};"
        : "+f"(c[0]), "+f"(c[1]), "+f"(c[2]), "+f"(c[3])
        : "r"(a[0]), "r"(a[1]), "r"(a[2]), "r"(a[3]), "r"(b[0]), "r"(b[1]));
}

// ---- prep: one-time tables -------------------------------------------------
__global__ __launch_bounds__(256) void prep_kernel(
    const float* __restrict__ W, const float* __restrict__ b,
    const float* __restrict__ fm,
    const float* __restrict__ g1, const float* __restrict__ be1,
    const float* __restrict__ m1, const float* __restrict__ v1,
    const float* __restrict__ g2, const float* __restrict__ be2,
    const float* __restrict__ m2, const float* __restrict__ v2)
{
    int i = blockIdx.x * 256 + threadIdx.x;   // 0..4095
    if (i < 2048) {
        int kp = i >> 6, u = i & 63;
        float m0 = 0.0f, m1v = 0.0f;
        if (u < Vn) {
            m0 = tanhf(fm[u * Cn + 2 * kp]) + 1.0f;
            m1v = tanhf(fm[u * Cn + 2 * kp + 1]) + 1.0f;
        }
        d_mP[i] = make_float2(m0, m1v);
    }
    if (i < 4096) {
        // W^T fp16, padded rows: i = c*64+d
        int c = i >> 6, d = i & 63;
        d_WhH[d * RS + c] = __float2half(W[i]);

        // BN1 packed: i = u*64+d -> store at [d*64+u]
        int u = i >> 6, dd = i & 63;
        float a = g1[i] * rsqrtf(v1[i] + 1e-5f);
        d_AB1[dd * 64 + u] = make_float2(a, be1[i] + a * (b[dd] - m1[i]));
    }
    if (i < Dn) {
        float a = g2[i] * rsqrtf(v2[i] + 1e-5f);
        d_A2[i] = a;
        d_B2[i] = be2[i] - a * m2[i];
    }
}

// ---- kernelA: shift+mask -> fp16 2-pass mma GEMM -> BN1+ReLU+inv shift -----
// Static smem 27648 B: AH[0,9216) AL[9216,18432) BH[18432,27648)
// A rows use XOR swizzle on k-word index: kw' = kw ^ ((u>>3)&3).
// Stage (3520 floats = 14080 B) overlays AH/AL after GEMM.
__global__ __launch_bounds__(256) void kernelA(const float* __restrict__ x)
{
    __shared__ __align__(16) char smraw[27648];
    __half* AH = (__half*)smraw;                 // [u*RS + k], swizzled
    __half* AL = AH + 64 * RS;
    __half* BH = AL + 64 * RS;                   // [d*RS + k]
    unsigned* AHw = (unsigned*)AH;
    unsigned* ALw = (unsigned*)AL;
    const unsigned* BHw = (const unsigned*)BH;

    const int tid = threadIdx.x;
    const int nt = blockIdx.x;
    const int n = nt >> 7;
    const int t = nt & 127;

    // Copy W tile (pre-converted): 9216 B = 576 float4
    {
        float4* bh4 = (float4*)BH;
        const float4* gh4 = (const float4*)d_WhH;
        for (int i = tid; i < 576; i += 256) bh4[i] = gh4[i];
    }

    // Build A: lanes span u (coalesced x reads), k-pair fixed per warp.
    // A[u][k] = x[n,k,t,(u+k)%55] * m[k][u]; zero pad rows u=55..63.
    const float* xnt = x + ((size_t)n * Cn * Tn + t) * Vn;
    for (int iw = tid; iw < 2048; iw += 256) {
        int u  = (iw & 31) + ((iw >> 10) << 5);
        int kp = (iw >> 5) & 31;
        int k  = kp << 1;
        float v0 = 0.0f, v1 = 0.0f;
        if (u < Vn) {
            int s0 = u + k;
            if (s0 >= Vn) s0 -= Vn;
            if (s0 >= Vn) s0 -= Vn;
            int s1 = s0 + 1;
            if (s1 >= Vn) s1 -= Vn;
            float2 m2v = d_mP[kp * 64 + u];
            v0 = xnt[(size_t)k * (Tn * Vn) + s0] * m2v.x;
            v1 = xnt[(size_t)(k + 1) * (Tn * Vn) + s1] * m2v.y;
        }
        __half2 h2 = __float22half2_rn(make_float2(v0, v1));
        float l0 = v0 - __half2float(__low2half(h2));
        float l1 = v1 - __half2float(__high2half(h2));
        __half2 l2 = __float22half2_rn(make_float2(l0, l1));
        int kws = kp ^ ((u >> 3) & 3);            // XOR swizzle
        AHw[u * 36 + kws] = *(unsigned*)&h2;
        ALw[u * 36 + kws] = *(unsigned*)&l2;
    }
    __syncthreads();

    // GEMM: y[u][d] = sum_k A[u][k] * WT[d][k].  M=64 N=64 K=64, 2 passes.
    const int w = tid >> 5;
    const int lane = tid & 31;
    const int lr = lane >> 2;
    const int lc = lane & 3;
    const int ub = (w & 3) * 16;
    const int nb = (w >> 2) * 32;
    const int row0 = ub + lr;
    const int row1 = row0 + 8;
    const int lcs0 = lc ^ ((row0 >> 3) & 3);
    const int lcs1 = lc ^ ((row1 >> 3) & 3);

    float acc[4][4];
#pragma unroll
    for (int i = 0; i < 4; i++)
#pragma unroll
        for (int j = 0; j < 4; j++) acc[i][j] = 0.0f;

#pragma unroll
    for (int s = 0; s < 4; s++) {               // k0 = s*16
        const int a0 = row0 * 36 + s * 8 + lcs0;
        const int a1 = row1 * 36 + s * 8 + lcs1;
        unsigned ah[4], al[4];
        ah[0] = AHw[a0];
        ah[1] = AHw[a1];
        ah[2] = AHw[a0 + 4];
        ah[3] = AHw[a1 + 4];
        al[0] = ALw[a0];
        al[1] = ALw[a1];
        al[2] = ALw[a0 + 4];
        al[3] = ALw[a1 + 4];
#pragma unroll
        for (int ntile = 0; ntile < 4; ntile++) {
            const int bbase = (nb + ntile * 8 + lr) * 36 + s * 8 + lc;
            unsigned bh[2];
            bh[0] = BHw[bbase];
            bh[1] = BHw[bbase + 4];
            mma16(acc[ntile], ah, bh);
            mma16(acc[ntile], al, bh);
        }
    }
    __syncthreads();   // GEMM smem reads done; A region becomes staging

    // Epilogue: BN1 + ReLU + inverse shift into stage[d*55 + (u+d)%55]
    float* stage = (float*)smraw;
#pragma unroll
    for (int i = 0; i < 4; i++) {
        int u = ub + lr + ((i & 2) ? 8 : 0);
        if (u < Vn) {
#pragma unroll
            for (int ntile = 0; ntile < 4; ntile++) {
                int d = nb + ntile * 8 + lc * 2 + (i & 1);
                float2 ab = d_AB1[d * 64 + u];
                float y = fmaxf(ab.x * acc[ntile][i] + ab.y, 0.0f);
                int vv = u + d;
                if (vv >= Vn) vv -= Vn;
                if (vv >= Vn) vv -= Vn;
                stage[d * Vn + vv] = y;
            }
        }
    }
    __syncthreads();

    // Store g in [n][d][t][v] layout (matches x/out layout for kernelB)
    {
        float* gn = g_buf + (size_t)n * (Cn * Tn * Vn) + t * Vn;
        for (int i = tid; i < VD; i += 256) {
            int d = i / 55;
            int v = i - d * 55;
            gn[(size_t)d * (Tn * Vn) + v] = stage[i];
        }
    }
}

// ---- kernelB: temporal shift + BN2 + residual + ReLU (8 elems/thread) ------
// g_buf now has identical indexing to x/out: g read = g[i0 + off*55].
__global__ __launch_bounds__(256) void kernelB(const float* __restrict__ x,
                                               float* __restrict__ out)
{
    int gid = blockIdx.x * 256 + threadIdx.x;   // < 3,604,480
    int i0 = gid * 8;
    int nc = i0 / 7040;                // 7040 = 128t*55v per (n,c); 8 | 7040
    int rem = i0 - nc * 7040;
    int c = nc & 63;
    float a2 = d_A2[c], b2 = d_B2[c];
    int off = (c % 3) - 1;
    const float* gq = g_buf + i0 + off * 55;

    float4 xv0 = *(const float4*)(x + i0);
    float4 xv1 = *(const float4*)(x + i0 + 4);
    float xr[8] = {xv0.x, xv0.y, xv0.z, xv0.w, xv1.x, xv1.y, xv1.z, xv1.w};

    int t = rem / 55;
    int v = rem - t * 55;
    float r[8];
#pragma unroll
    for (int e = 0; e < 8; e++) {
        int tt = t + off;
        float gv = 0.0f;
        if ((unsigned)tt < (unsigned)Tn) gv = gq[e];
        r[e] = fmaxf(a2 * gv + b2 + xr[e], 0.0f);
        if (++v == 55) { v = 0; t++; }
    }
    *(float4*)(out + i0)     = make_float4(r[0], r[1], r[2], r[3]);
    *(float4*)(out + i0 + 4) = make_float4(r[4], r[5], r[6], r[7]);
}

extern "C" void kernel_launch(void* const* d_in, const int* in_sizes, int n_in,
                              void* d_out, int out_size)
{
    const float* x   = (const float*)d_in[0];
    const float* W   = (const float*)d_in[1];
    const float* b   = (const float*)d_in[2];
    const float* fm  = (const float*)d_in[3];
    const float* g1  = (const float*)d_in[4];
    const float* be1 = (const float*)d_in[5];
    const float* m1  = (const float*)d_in[6];
    const float* v1  = (const float*)d_in[7];
    const float* g2  = (const float*)d_in[8];
    const float* be2 = (const float*)d_in[9];
    const float* m2  = (const float*)d_in[10];
    const float* v2  = (const float*)d_in[11];
    float* out = (float*)d_out;

    prep_kernel<<<16, 256>>>(W, b, fm, g1, be1, m1, v1, g2, be2, m2, v2);
    kernelA<<<NTn, 256>>>(x);
    kernelB<<<TOTAL / 2048, 256>>>(x, out);
}

// round 14
// speedup vs baseline: 1.7746x; 1.2233x over previous
#include <cuda_runtime.h>
#include <cuda_fp16.h>
#include <cstdint>

#define Vn 55
#define Cn 64
#define Dn 64
#define Tn 128
#define Nn 64
#define NTn 8192
#define VD 3520
#define TOTAL (NTn * VD)       // 28,835,840

#define RS 72                  // padded row stride in fp16 elements (36 words)

__device__ __half g_buf[TOTAL];           // g fp16 in [n][t][d*55+v]
__device__ float2 d_mP[2048];             // mask pairs: [kp*64+u]
__device__ float2 d_AB1[4096];            // BN1 (scale, shift) packed, [d*64+u]
__device__ float d_A2[Dn];
__device__ float d_B2[Dn];
__device__ __half d_WhH[64 * RS];         // W^T fp16, [d*RS + c]

__device__ __forceinline__ void mma16(float* c, const unsigned* a, const unsigned* b) {
    asm volatile(
        "mma.sync.aligned.m16n8k16.row.col.f32.f16.f16.f32 "
        "{%0,%1,%2,%3}, {%4,%5,%6,%7}, {%8,%9}, {%0,%1,%2,%3};"
        : "+f"(c[0]), "+f"(c[1]), "+f"(c[2]), "+f"(c[3])
        : "r"(a[0]), "r"(a[1]), "r"(a[2]), "r"(a[3]), "r"(b[0]), "r"(b[1]));
}

// ---- prep: one-time tables -------------------------------------------------
__global__ __launch_bounds__(256) void prep_kernel(
    const float* __restrict__ W, const float* __restrict__ b,
    const float* __restrict__ fm,
    const float* __restrict__ g1, const float* __restrict__ be1,
    const float* __restrict__ m1, const float* __restrict__ v1,
    const float* __restrict__ g2, const float* __restrict__ be2,
    const float* __restrict__ m2, const float* __restrict__ v2)
{
    int i = blockIdx.x * 256 + threadIdx.x;   // 0..4095
    if (i < 2048) {
        int kp = i >> 6, u = i & 63;
        float m0 = 0.0f, m1v = 0.0f;
        if (u < Vn) {
            m0 = tanhf(fm[u * Cn + 2 * kp]) + 1.0f;
            m1v = tanhf(fm[u * Cn + 2 * kp + 1]) + 1.0f;
        }
        d_mP[i] = make_float2(m0, m1v);
    }
    if (i < 4096) {
        // W^T fp16, padded rows: i = c*64+d
        int c = i >> 6, d = i & 63;
        d_WhH[d * RS + c] = __float2half(W[i]);

        // BN1 packed: i = u*64+d -> store at [d*64+u]
        int u = i >> 6, dd = i & 63;
        float a = g1[i] * rsqrtf(v1[i] + 1e-5f);
        d_AB1[dd * 64 + u] = make_float2(a, be1[i] + a * (b[dd] - m1[i]));
    }
    if (i < Dn) {
        float a = g2[i] * rsqrtf(v2[i] + 1e-5f);
        d_A2[i] = a;
        d_B2[i] = be2[i] - a * m2[i];
    }
}

// ---- kernelA: shift+mask -> fp16 2-pass mma GEMM -> BN1+ReLU+inv shift -----
// Static smem 27648 B: AH[0,9216) AL[9216,18432) BH[18432,27648)
// A rows use XOR swizzle on k-word index: kw' = kw ^ ((u>>3)&3).
// Stage (3520 floats = 14080 B) overlays AH/AL after GEMM.
__global__ __launch_bounds__(256) void kernelA(const float* __restrict__ x)
{
    __shared__ __align__(16) char smraw[27648];
    __half* AH = (__half*)smraw;                 // [u*RS + k], swizzled
    __half* AL = AH + 64 * RS;
    __half* BH = AL + 64 * RS;                   // [d*RS + k]
    unsigned* AHw = (unsigned*)AH;
    unsigned* ALw = (unsigned*)AL;
    const unsigned* BHw = (const unsigned*)BH;

    const int tid = threadIdx.x;
    const int nt = blockIdx.x;
    const int n = nt >> 7;
    const int t = nt & 127;

    // Copy W tile (pre-converted): 9216 B = 576 float4
    {
        float4* bh4 = (float4*)BH;
        const float4* gh4 = (const float4*)d_WhH;
        for (int i = tid; i < 576; i += 256) bh4[i] = gh4[i];
    }

    // Build A: lanes span u (coalesced x reads), k-pair fixed per warp.
    const float* xnt = x + ((size_t)n * Cn * Tn + t) * Vn;
    for (int iw = tid; iw < 2048; iw += 256) {
        int u  = (iw & 31) + ((iw >> 10) << 5);
        int kp = (iw >> 5) & 31;
        int k  = kp << 1;
        float v0 = 0.0f, v1 = 0.0f;
        if (u < Vn) {
            int s0 = u + k;
            if (s0 >= Vn) s0 -= Vn;
            if (s0 >= Vn) s0 -= Vn;
            int s1 = s0 + 1;
            if (s1 >= Vn) s1 -= Vn;
            float2 m2v = d_mP[kp * 64 + u];
            v0 = xnt[(size_t)k * (Tn * Vn) + s0] * m2v.x;
            v1 = xnt[(size_t)(k + 1) * (Tn * Vn) + s1] * m2v.y;
        }
        __half2 h2 = __float22half2_rn(make_float2(v0, v1));
        float l0 = v0 - __half2float(__low2half(h2));
        float l1 = v1 - __half2float(__high2half(h2));
        __half2 l2 = __float22half2_rn(make_float2(l0, l1));
        int kws = kp ^ ((u >> 3) & 3);            // XOR swizzle
        AHw[u * 36 + kws] = *(unsigned*)&h2;
        ALw[u * 36 + kws] = *(unsigned*)&l2;
    }
    __syncthreads();

    // GEMM: y[u][d] = sum_k A[u][k] * WT[d][k].  M=64 N=64 K=64, 2 passes.
    const int w = tid >> 5;
    const int lane = tid & 31;
    const int lr = lane >> 2;
    const int lc = lane & 3;
    const int ub = (w & 3) * 16;
    const int nb = (w >> 2) * 32;
    const int row0 = ub + lr;
    const int row1 = row0 + 8;
    const int lcs0 = lc ^ ((row0 >> 3) & 3);
    const int lcs1 = lc ^ ((row1 >> 3) & 3);

    float acc[4][4];
#pragma unroll
    for (int i = 0; i < 4; i++)
#pragma unroll
        for (int j = 0; j < 4; j++) acc[i][j] = 0.0f;

#pragma unroll
    for (int s = 0; s < 4; s++) {               // k0 = s*16
        const int a0 = row0 * 36 + s * 8 + lcs0;
        const int a1 = row1 * 36 + s * 8 + lcs1;
        unsigned ah[4], al[4];
        ah[0] = AHw[a0];
        ah[1] = AHw[a1];
        ah[2] = AHw[a0 + 4];
        ah[3] = AHw[a1 + 4];
        al[0] = ALw[a0];
        al[1] = ALw[a1];
        al[2] = ALw[a0 + 4];
        al[3] = ALw[a1 + 4];
#pragma unroll
        for (int ntile = 0; ntile < 4; ntile++) {
            const int bbase = (nb + ntile * 8 + lr) * 36 + s * 8 + lc;
            unsigned bh[2];
            bh[0] = BHw[bbase];
            bh[1] = BHw[bbase + 4];
            mma16(acc[ntile], ah, bh);
            mma16(acc[ntile], al, bh);
        }
    }
    __syncthreads();   // GEMM smem reads done; A region becomes staging

    // Epilogue: BN1 + ReLU + inverse shift into stage[d*55 + (u+d)%55]
    float* stage = (float*)smraw;
#pragma unroll
    for (int i = 0; i < 4; i++) {
        int u = ub + lr + ((i & 2) ? 8 : 0);
        if (u < Vn) {
#pragma unroll
            for (int ntile = 0; ntile < 4; ntile++) {
                int d = nb + ntile * 8 + lc * 2 + (i & 1);
                float2 ab = d_AB1[d * 64 + u];
                float y = fmaxf(ab.x * acc[ntile][i] + ab.y, 0.0f);
                int vv = u + d;
                if (vv >= Vn) vv -= Vn;
                if (vv >= Vn) vv -= Vn;
                stage[d * Vn + vv] = y;
            }
        }
    }
    __syncthreads();

    // Coalesced fp16 store g[n][t][d*55+v]
    {
        unsigned* gn = (unsigned*)(g_buf + (size_t)nt * VD);   // 4B aligned (VD even)
        for (int j = tid; j < 1760; j += 256) {
            float2 f2 = *(const float2*)(stage + 2 * j);
            __half2 h2 = __float22half2_rn(f2);
            gn[j] = *(unsigned*)&h2;
        }
    }
}

// ---- kernelB: temporal shift + BN2 + residual + ReLU (8 elems/thread) ------
__global__ __launch_bounds__(256) void kernelB(const float* __restrict__ x,
                                               float* __restrict__ out)
{
    int gid = blockIdx.x * 256 + threadIdx.x;   // < 3,604,480
    int i0 = gid * 8;
    int nc = i0 / 7040;                // 7040 = 128t*55v per (n,c); 8 | 7040
    int rem = i0 - nc * 7040;
    int c = nc & 63;
    int n = nc >> 6;
    float a2 = d_A2[c], b2 = d_B2[c];
    int off = (c % 3) - 1;
    const __half* gB = g_buf + (size_t)(n * Tn) * VD + c * Vn;

    float4 xv0 = *(const float4*)(x + i0);
    float4 xv1 = *(const float4*)(x + i0 + 4);
    float xr[8] = {xv0.x, xv0.y, xv0.z, xv0.w, xv1.x, xv1.y, xv1.z, xv1.w};

    int t = rem / 55;
    int v = rem - t * 55;
    float r[8];
#pragma unroll
    for (int e = 0; e < 8; e++) {
        int tt = t + off;
        float gv = 0.0f;
        if ((unsigned)tt < (unsigned)Tn) gv = __half2float(gB[(size_t)tt * VD + v]);
        r[e] = fmaxf(a2 * gv + b2 + xr[e], 0.0f);
        if (++v == 55) { v = 0; t++; }
    }
    *(float4*)(out + i0)     = make_float4(r[0], r[1], r[2], r[3]);
    *(float4*)(out + i0 + 4) = make_float4(r[4], r[5], r[6], r[7]);
}

extern "C" void kernel_launch(void* const* d_in, const int* in_sizes, int n_in,
                              void* d_out, int out_size)
{
    const float* x   = (const float*)d_in[0];
    const float* W   = (const float*)d_in[1];
    const float* b   = (const float*)d_in[2];
    const float* fm  = (const float*)d_in[3];
    const float* g1  = (const float*)d_in[4];
    const float* be1 = (const float*)d_in[5];
    const float* m1  = (const float*)d_in[6];
    const float* v1  = (const float*)d_in[7];
    const float* g2  = (const float*)d_in[8];
    const float* be2 = (const float*)d_in[9];
    const float* m2  = (const float*)d_in[10];
    const float* v2  = (const float*)d_in[11];
    float* out = (float*)d_out;

    prep_kernel<<<16, 256>>>(W, b, fm, g1, be1, m1, v1, g2, be2, m2, v2);
    kernelA<<<NTn, 256>>>(x);
    kernelB<<<TOTAL / 2048, 256>>>(x, out);
}